// round 1
// baseline (speedup 1.0000x reference)
#include <cuda_runtime.h>

#define CPG 42
#define IMG 192

// Block: one (channel, qz, qy) tile -> 5x5 (z,y) output rows x 192 x-outputs.
// 240 threads: tid%48 = float4 x-group, tid/48 = rz.
__global__ __launch_bounds__(240) void ffd_kernel(const float* __restrict__ v,
                                                  float* __restrict__ out) {
    const int qy = blockIdx.x;   // 0..38
    const int qz = blockIdx.y;   // 0..38
    const int ch = blockIdx.z;   // 0..11

    __shared__ float s_W[5][4];          // B-spline weights per residue
    __shared__ float s_cp[4][4][CPG];    // control points [dz][dy][cx]
    __shared__ float s_tz[5][4][CPG];    // z-collapsed   [rz][dy][cx]
    __shared__ float s_row[25][CPG];     // zy-collapsed  [rz*5+ry][cx]

    const int tid = threadIdx.x;

    // weight table
    if (tid < 20) {
        int r = tid >> 2, d = tid & 3;
        float u = (float)r * 0.2f;
        float w;
        if (d == 0)      { float a = 1.0f - u; w = a * a * a * (1.0f / 6.0f); }
        else if (d == 1) { w = (3.0f * u * u * u - 6.0f * u * u + 4.0f) * (1.0f / 6.0f); }
        else if (d == 2) { w = (((-3.0f * u + 3.0f) * u + 3.0f) * u + 1.0f) * (1.0f / 6.0f); }
        else             { w = u * u * u * (1.0f / 6.0f); }
        s_W[r][d] = w;
    }

    // Phase A: load 4x4x42 control-point slab
    const float* vc = v + (size_t)ch * (CPG * CPG * CPG);
    for (int i = tid; i < 4 * 4 * CPG; i += 240) {
        int cx = i % CPG;
        int t = i / CPG;
        int dy = t & 3, dz = t >> 2;
        s_cp[dz][dy][cx] = vc[((size_t)(qz + dz) * CPG + (qy + dy)) * CPG + cx];
    }
    __syncthreads();

    // Phase B1: collapse z  (5*4*42 elems, 4 FMA each)
    for (int i = tid; i < 5 * 4 * CPG; i += 240) {
        int cx = i % CPG;
        int t = i / CPG;
        int dy = t & 3, rz = t >> 2;
        float acc = s_W[rz][0] * s_cp[0][dy][cx];
        acc = fmaf(s_W[rz][1], s_cp[1][dy][cx], acc);
        acc = fmaf(s_W[rz][2], s_cp[2][dy][cx], acc);
        acc = fmaf(s_W[rz][3], s_cp[3][dy][cx], acc);
        s_tz[rz][dy][cx] = acc;
    }
    __syncthreads();

    // Phase B2: collapse y  (25*42 elems, 4 FMA each)
    for (int i = tid; i < 25 * CPG; i += 240) {
        int cx = i % CPG;
        int rr = i / CPG;
        int ry = rr % 5, rz = rr / 5;
        float acc = s_W[ry][0] * s_tz[rz][0][cx];
        acc = fmaf(s_W[ry][1], s_tz[rz][1][cx], acc);
        acc = fmaf(s_W[ry][2], s_tz[rz][2][cx], acc);
        acc = fmaf(s_W[ry][3], s_tz[rz][3][cx], acc);
        s_row[rr][cx] = acc;
    }
    __syncthreads();

    // Phase C: x expansion. Each thread owns a fixed float4 (4 x-outputs) and a
    // fixed rz; loops over 5 ry rows.
    const int x4 = tid % 48;
    const int rz = tid / 48;          // 0..4
    const int x0 = x4 * 4;
    const int q  = x0 / 5;            // leftmost control tap; q+4 <= 41

    // Merged per-thread weights: out[j] = sum_e we[j][e] * row[q+e]
    float we[4][5];
    #pragma unroll
    for (int j = 0; j < 4; j++) {
        int xx = x0 + j;
        int qq = xx / 5;
        int rx = xx - qq * 5;
        int s = qq - q;               // 0 or 1
        float u = (float)rx * 0.2f;
        float a = 1.0f - u;
        float w0 = a * a * a * (1.0f / 6.0f);
        float w1 = (3.0f * u * u * u - 6.0f * u * u + 4.0f) * (1.0f / 6.0f);
        float w2 = (((-3.0f * u + 3.0f) * u + 3.0f) * u + 1.0f) * (1.0f / 6.0f);
        float w3 = u * u * u * (1.0f / 6.0f);
        we[j][0] = s ? 0.0f : w0;
        we[j][1] = s ? w0 : w1;
        we[j][2] = s ? w1 : w2;
        we[j][3] = s ? w2 : w3;
        we[j][4] = s ? w3 : 0.0f;
    }

    const int z = qz * 5 + rz;
    if (z >= IMG) return;
    const int y0 = qy * 5;
    float* op = out + ((size_t)ch * IMG + z) * IMG * IMG + (size_t)y0 * IMG + x0;

    #pragma unroll
    for (int ry = 0; ry < 5; ry++) {
        if (y0 + ry >= IMG) break;
        const float* rp = &s_row[rz * 5 + ry][q];
        float r0 = rp[0], r1 = rp[1], r2 = rp[2], r3 = rp[3], r4 = rp[4];
        float4 o;
        o.x = fmaf(we[0][0], r0, fmaf(we[0][1], r1, fmaf(we[0][2], r2,
              fmaf(we[0][3], r3, we[0][4] * r4))));
        o.y = fmaf(we[1][0], r0, fmaf(we[1][1], r1, fmaf(we[1][2], r2,
              fmaf(we[1][3], r3, we[1][4] * r4))));
        o.z = fmaf(we[2][0], r0, fmaf(we[2][1], r1, fmaf(we[2][2], r2,
              fmaf(we[2][3], r3, we[2][4] * r4))));
        o.w = fmaf(we[3][0], r0, fmaf(we[3][1], r1, fmaf(we[3][2], r2,
              fmaf(we[3][3], r3, we[3][4] * r4))));
        __stcs(reinterpret_cast<float4*>(op + (size_t)ry * IMG), o);
    }
}

extern "C" void kernel_launch(void* const* d_in, const int* in_sizes, int n_in,
                              void* d_out, int out_size) {
    const float* v = (const float*)d_in[0];
    float* out = (float*)d_out;
    dim3 grid(39, 39, 12);   // (qy, qz, channel)
    ffd_kernel<<<grid, 240>>>(v, out);
}

// round 2
// speedup vs baseline: 1.4047x; 1.4047x over previous
#include <cuda_runtime.h>

#define CPG 42
#define IMG 192
#define CPG3 (CPG * CPG * CPG)
#define IMG2 ((size_t)IMG * IMG)
#define IMG3 ((size_t)IMG * IMG * IMG)

// Block: one (qz, qy) tile across 4 channels. 240 threads.
// Phase C: tid%48 = float4 x-group, tid/48 = rz.
__global__ __launch_bounds__(240) void ffd_kernel(const float* __restrict__ v,
                                                  float* __restrict__ out) {
    const int qy = blockIdx.x;       // 0..38
    const int qz = blockIdx.y;       // 0..38
    const int chBase = blockIdx.z * 4;  // 0,4,8

    __shared__ float s_W[5][4];          // B-spline weights per residue
    __shared__ float s_we[100];          // phase-C class table [5 cls][4 j][5 e]
    __shared__ float s_cp[4][4][CPG];    // control points [dz][dy][cx]
    __shared__ float s_tz[5][4][CPG];    // z-collapsed   [rz][dy][cx]
    __shared__ float s_row[25][CPG];     // zy-collapsed  [rz*5+ry][cx]

    const int tid = threadIdx.x;

    // ---- one-time weight tables ----
    if (tid < 20) {
        int r = tid >> 2, d = tid & 3;
        float u = (float)r * 0.2f;
        float w;
        if (d == 0)      { float a = 1.0f - u; w = a * a * a * (1.0f / 6.0f); }
        else if (d == 1) { w = (3.0f * u * u * u - 6.0f * u * u + 4.0f) * (1.0f / 6.0f); }
        else if (d == 2) { w = (((-3.0f * u + 3.0f) * u + 3.0f) * u + 1.0f) * (1.0f / 6.0f); }
        else             { w = u * u * u * (1.0f / 6.0f); }
        s_W[r][d] = w;
    } else if (tid < 40) {
        // class table: class c = x4 % 5, representative x0 = 4c
        int tt = tid - 20;
        int c = tt >> 2, j = tt & 3;
        int xx = 4 * c + j;
        int qq = xx / 5;
        int rx = xx - qq * 5;
        int s = qq - ((4 * c) / 5);     // 0 or 1
        float u = (float)rx * 0.2f;
        float a = 1.0f - u;
        float w0 = a * a * a * (1.0f / 6.0f);
        float w1 = (3.0f * u * u * u - 6.0f * u * u + 4.0f) * (1.0f / 6.0f);
        float w2 = (((-3.0f * u + 3.0f) * u + 3.0f) * u + 1.0f) * (1.0f / 6.0f);
        float w3 = u * u * u * (1.0f / 6.0f);
        float* p = &s_we[(c * 4 + j) * 5];
        p[0] = s ? 0.0f : w0;
        p[1] = s ? w0 : w1;
        p[2] = s ? w1 : w2;
        p[3] = s ? w2 : w3;
        p[4] = s ? w3 : 0.0f;
    }

    // ---- one-time per-thread index derivation ----
    const int cx0 = tid % CPG;       // base for incremental divmod (stride 240 = 5*42+30)
    const int t0  = tid / CPG;

    const int x4  = tid % 48;        // phase C float4 group
    const int rz  = tid / 48;        // 0..4
    const int x0  = x4 * 4;
    const int q   = x0 / 5;          // leftmost tap; q+4 <= 41
    const int cls = x4 % 5;

    const int z  = qz * 5 + rz;
    const int y0 = qy * 5;
    const bool zok = (z < IMG);
    const size_t zoff = (size_t)z * IMG2 + (size_t)y0 * IMG + (size_t)x0;

    __syncthreads();

    // phase-C weights -> registers (20 conflict-free LDS, once)
    float we[4][5];
    {
        const float* p = &s_we[cls * 20];
        #pragma unroll
        for (int j = 0; j < 4; j++)
            #pragma unroll
            for (int e = 0; e < 5; e++)
                we[j][e] = p[j * 5 + e];
    }

    const float* s_rowq = &s_row[rz * 5][0] + q;   // base for phase C reads

    for (int cc = 0; cc < 4; cc++) {
        const int ch = chBase + cc;
        const float* vc = v + (size_t)ch * CPG3;

        // Phase A: load 4x4x42 control-point slab (16 rows)
        {
            int i = tid, cx = cx0, t = t0;
            while (i < 16 * CPG) {
                int dz = t >> 2, dy = t & 3;
                s_cp[dz][dy][cx] =
                    vc[((size_t)(qz + dz) * CPG + (qy + dy)) * CPG + cx];
                i += 240; cx += 30; t += 5;
                if (cx >= CPG) { cx -= CPG; t += 1; }
            }
        }
        __syncthreads();

        // Phase B1: collapse z (20 rows x 42)
        {
            int i = tid, cx = cx0, t = t0;
            while (i < 20 * CPG) {
                int rzz = t >> 2, dy = t & 3;
                float acc = s_W[rzz][0] * s_cp[0][dy][cx];
                acc = fmaf(s_W[rzz][1], s_cp[1][dy][cx], acc);
                acc = fmaf(s_W[rzz][2], s_cp[2][dy][cx], acc);
                acc = fmaf(s_W[rzz][3], s_cp[3][dy][cx], acc);
                s_tz[rzz][dy][cx] = acc;
                i += 240; cx += 30; t += 5;
                if (cx >= CPG) { cx -= CPG; t += 1; }
            }
        }
        __syncthreads();

        // Phase B2: collapse y (25 rows x 42)
        {
            int i = tid, cx = cx0, t = t0;
            while (i < 25 * CPG) {
                int rzz = t / 5, ry = t - rzz * 5;
                float acc = s_W[ry][0] * s_tz[rzz][0][cx];
                acc = fmaf(s_W[ry][1], s_tz[rzz][1][cx], acc);
                acc = fmaf(s_W[ry][2], s_tz[rzz][2][cx], acc);
                acc = fmaf(s_W[ry][3], s_tz[rzz][3][cx], acc);
                s_row[t][cx] = acc;
                i += 240; cx += 30; t += 5;
                if (cx >= CPG) { cx -= CPG; t += 1; }
            }
        }
        __syncthreads();

        // Phase C: x expansion, 5 ry rows per thread, float4 stores
        float* op = out + (size_t)ch * IMG3 + zoff;
        #pragma unroll
        for (int ry = 0; ry < 5; ry++) {
            const float* rp = s_rowq + ry * CPG;
            float r0 = rp[0], r1 = rp[1], r2 = rp[2], r3 = rp[3], r4 = rp[4];
            float4 o;
            o.x = fmaf(we[0][0], r0, fmaf(we[0][1], r1, fmaf(we[0][2], r2,
                  fmaf(we[0][3], r3, we[0][4] * r4))));
            o.y = fmaf(we[1][0], r0, fmaf(we[1][1], r1, fmaf(we[1][2], r2,
                  fmaf(we[1][3], r3, we[1][4] * r4))));
            o.z = fmaf(we[2][0], r0, fmaf(we[2][1], r1, fmaf(we[2][2], r2,
                  fmaf(we[2][3], r3, we[2][4] * r4))));
            o.w = fmaf(we[3][0], r0, fmaf(we[3][1], r1, fmaf(we[3][2], r2,
                  fmaf(we[3][3], r3, we[3][4] * r4))));
            if (zok && (y0 + ry < IMG))
                __stcs(reinterpret_cast<float4*>(op + (size_t)ry * IMG), o);
        }
        // no sync needed here: next phase A's barrier orders s_row reads
        // before the next channel's B2 writes
    }
}

extern "C" void kernel_launch(void* const* d_in, const int* in_sizes, int n_in,
                              void* d_out, int out_size) {
    const float* v = (const float*)d_in[0];
    float* out = (float*)d_out;
    dim3 grid(39, 39, 3);   // (qy, qz, channel-group of 4)
    ffd_kernel<<<grid, 240>>>(v, out);
}

// round 3
// speedup vs baseline: 2.0378x; 1.4507x over previous
#include <cuda_runtime.h>

#define CPG 42
#define IMG 192
#define CPG3 (CPG * CPG * CPG)
#define IMG2 ((size_t)IMG * IMG)
#define IMG3 (IMG2 * IMG)

// Block: one (qz, qy) tile across 4 channels. 256 threads (8 full warps).
__global__ __launch_bounds__(256) void ffd_kernel(const float* __restrict__ v,
                                                  float* __restrict__ out) {
    const int qy = blockIdx.x;          // 0..38
    const int qz = blockIdx.y;          // 0..38
    const int chBase = blockIdx.z * 4;  // 0,4,8

    __shared__ float s_W[5][4];         // B-spline weights per residue
    __shared__ float s_we[100];         // phase-C class table [5 cls][4 j][5 e]
    __shared__ float s_cp[16][CPG];     // control points [(dz*4+dy)][cx]
    __shared__ float s_row[25][CPG];    // zy-collapsed  [rz*5+ry][cx]

    const int tid = threadIdx.x;

    // ---- one-time weight tables ----
    if (tid < 20) {
        int r = tid >> 2, d = tid & 3;
        float u = (float)r * 0.2f;
        float w;
        if (d == 0)      { float a = 1.0f - u; w = a * a * a * (1.0f / 6.0f); }
        else if (d == 1) { w = (3.0f * u * u * u - 6.0f * u * u + 4.0f) * (1.0f / 6.0f); }
        else if (d == 2) { w = (((-3.0f * u + 3.0f) * u + 3.0f) * u + 1.0f) * (1.0f / 6.0f); }
        else             { w = u * u * u * (1.0f / 6.0f); }
        s_W[r][d] = w;
    } else if (tid < 40) {
        int tt = tid - 20;
        int c = tt >> 2, j = tt & 3;
        int xx = 4 * c + j;
        int qq = xx / 5;
        int rx = xx - qq * 5;
        int s = qq - ((4 * c) / 5);     // 0 or 1
        float u = (float)rx * 0.2f;
        float a = 1.0f - u;
        float w0 = a * a * a * (1.0f / 6.0f);
        float w1 = (3.0f * u * u * u - 6.0f * u * u + 4.0f) * (1.0f / 6.0f);
        float w2 = (((-3.0f * u + 3.0f) * u + 3.0f) * u + 1.0f) * (1.0f / 6.0f);
        float w3 = u * u * u * (1.0f / 6.0f);
        float* p = &s_we[(c * 4 + j) * 5];
        p[0] = s ? 0.0f : w0;
        p[1] = s ? w0 : w1;
        p[2] = s ? w1 : w2;
        p[3] = s ? w2 : w3;
        p[4] = s ? w3 : 0.0f;
    }

    // ---- per-thread mappings (computed once) ----
    // Phase B: thread = (brz, bcx), 210 active
    const int brz = tid / CPG;
    const int bcx = tid - brz * CPG;
    const bool bact = (tid < 210);

    // Phase C: thread = (rz, x-group), 240 active
    const int x4 = tid % 48;
    const int rz = tid / 48;
    const bool cact = (tid < 240);
    const int x0 = x4 * 4;
    const int q  = x0 / 5;              // q+4 <= 41
    const int cls = x4 % 5;
    const int z  = qz * 5 + rz;
    const int y0 = qy * 5;
    const size_t zoff = (size_t)z * IMG2 + (size_t)y0 * IMG + (size_t)x0;

    const float* vcBase = v + (size_t)chBase * CPG3 +
                          ((size_t)qz * CPG + qy) * CPG;

    // ---- Phase A for channel 0 ----
    #pragma unroll
    for (int i = tid; i < 16 * CPG; i += 256) {
        int r = i / CPG, c = i - (i / CPG) * CPG;
        s_cp[r][c] = vcBase[((size_t)(r >> 2) * CPG + (r & 3)) * CPG + c];
    }
    __syncthreads();

    // weights into registers
    float wz0 = 0.f, wz1 = 0.f, wz2 = 0.f, wz3 = 0.f;
    if (bact) { wz0 = s_W[brz][0]; wz1 = s_W[brz][1];
                wz2 = s_W[brz][2]; wz3 = s_W[brz][3]; }
    float we[4][5];
    if (cact) {
        const float* p = &s_we[cls * 20];
        #pragma unroll
        for (int j = 0; j < 4; j++)
            #pragma unroll
            for (int e = 0; e < 5; e++)
                we[j][e] = p[j * 5 + e];
    }

    const float* s_rowq = &s_row[rz * 5][0] + q;

    #pragma unroll
    for (int cc = 0; cc < 4; cc++) {
        // ---- Phase B (fused z+y collapse), 210 threads ----
        if (bact) {
            float tz[4];
            #pragma unroll
            for (int dy = 0; dy < 4; dy++) {
                float acc =        wz0 * s_cp[0 * 4 + dy][bcx];
                acc = fmaf(wz1, s_cp[1 * 4 + dy][bcx], acc);
                acc = fmaf(wz2, s_cp[2 * 4 + dy][bcx], acc);
                acc = fmaf(wz3, s_cp[3 * 4 + dy][bcx], acc);
                tz[dy] = acc;
            }
            #pragma unroll
            for (int ry = 0; ry < 5; ry++) {
                float acc =        s_W[ry][0] * tz[0];
                acc = fmaf(s_W[ry][1], tz[1], acc);
                acc = fmaf(s_W[ry][2], tz[2], acc);
                acc = fmaf(s_W[ry][3], tz[3], acc);
                s_row[brz * 5 + ry][bcx] = acc;
            }
        }
        __syncthreads();

        // ---- Phase A for next channel (overlaps with C) ----
        if (cc < 3) {
            const float* vcn = vcBase + (size_t)(cc + 1) * CPG3;
            #pragma unroll
            for (int i = tid; i < 16 * CPG; i += 256) {
                int r = i / CPG, c = i - (i / CPG) * CPG;
                s_cp[r][c] = vcn[((size_t)(r >> 2) * CPG + (r & 3)) * CPG + c];
            }
        }

        // ---- Phase C: x expansion ----
        if (cact) {
            float* op = out + (size_t)(chBase + cc) * IMG3 + zoff;
            const bool zok = (z < IMG);
            #pragma unroll
            for (int ry = 0; ry < 5; ry++) {
                const float* rp = s_rowq + ry * CPG;
                float r0 = rp[0], r1 = rp[1], r2 = rp[2], r3 = rp[3], r4 = rp[4];
                float4 o;
                o.x = fmaf(we[0][0], r0, fmaf(we[0][1], r1, fmaf(we[0][2], r2,
                      fmaf(we[0][3], r3, we[0][4] * r4))));
                o.y = fmaf(we[1][0], r0, fmaf(we[1][1], r1, fmaf(we[1][2], r2,
                      fmaf(we[1][3], r3, we[1][4] * r4))));
                o.z = fmaf(we[2][0], r0, fmaf(we[2][1], r1, fmaf(we[2][2], r2,
                      fmaf(we[2][3], r3, we[2][4] * r4))));
                o.w = fmaf(we[3][0], r0, fmaf(we[3][1], r1, fmaf(we[3][2], r2,
                      fmaf(we[3][3], r3, we[3][4] * r4))));
                if (zok && (y0 + ry < IMG))
                    __stcs(reinterpret_cast<float4*>(op + (size_t)ry * IMG), o);
            }
        }
        __syncthreads();   // s_row/s_cp consumed; next B may write
    }
}

extern "C" void kernel_launch(void* const* d_in, const int* in_sizes, int n_in,
                              void* d_out, int out_size) {
    const float* v = (const float*)d_in[0];
    float* out = (float*)d_out;
    dim3 grid(39, 39, 3);   // (qy, qz, channel-group of 4)
    ffd_kernel<<<grid, 256>>>(v, out);
}

// round 4
// speedup vs baseline: 2.1045x; 1.0328x over previous
#include <cuda_runtime.h>

#define CPG 42
#define IMG 192
#define CPG3 (CPG * CPG * CPG)
#define IMG2 ((size_t)IMG * IMG)
#define IMG3 (IMG2 * IMG)

// Block: one (qz, qy) tile across 4 channels, all channels batched per phase.
// 256 threads. Only 2 __syncthreads per block.
__global__ __launch_bounds__(256) void ffd_kernel(const float* __restrict__ v,
                                                  float* __restrict__ out) {
    const int qy = blockIdx.x;          // 0..38
    const int qz = blockIdx.y;          // 0..38
    const int chBase = blockIdx.z * 4;  // 0,4,8

    __shared__ float s_W[5][4];          // B-spline weights per residue
    __shared__ float s_we[100];          // phase-C class table [5 cls][4 j][5 e]
    __shared__ float s_cp[4][16][CPG];   // control points [ch][(dz*4+dy)][cx]
    __shared__ float s_row[4][25][CPG];  // zy-collapsed   [ch][rz*5+ry][cx]

    const int tid = threadIdx.x;

    // ---- one-time weight tables ----
    if (tid < 20) {
        int r = tid >> 2, d = tid & 3;
        float u = (float)r * 0.2f;
        float w;
        if (d == 0)      { float a = 1.0f - u; w = a * a * a * (1.0f / 6.0f); }
        else if (d == 1) { w = (3.0f * u * u * u - 6.0f * u * u + 4.0f) * (1.0f / 6.0f); }
        else if (d == 2) { w = (((-3.0f * u + 3.0f) * u + 3.0f) * u + 1.0f) * (1.0f / 6.0f); }
        else             { w = u * u * u * (1.0f / 6.0f); }
        s_W[r][d] = w;
    } else if (tid < 40) {
        int tt = tid - 20;
        int c = tt >> 2, j = tt & 3;
        int xx = 4 * c + j;
        int qq = xx / 5;
        int rx = xx - qq * 5;
        int s = qq - ((4 * c) / 5);     // 0 or 1
        float u = (float)rx * 0.2f;
        float a = 1.0f - u;
        float w0 = a * a * a * (1.0f / 6.0f);
        float w1 = (3.0f * u * u * u - 6.0f * u * u + 4.0f) * (1.0f / 6.0f);
        float w2 = (((-3.0f * u + 3.0f) * u + 3.0f) * u + 1.0f) * (1.0f / 6.0f);
        float w3 = u * u * u * (1.0f / 6.0f);
        float* p = &s_we[(c * 4 + j) * 5];
        p[0] = s ? 0.0f : w0;
        p[1] = s ? w0 : w1;
        p[2] = s ? w1 : w2;
        p[3] = s ? w2 : w3;
        p[4] = s ? w3 : 0.0f;
    }

    // ---- Phase A: load 4 channel slabs (4*16*42 = 2688 floats) ----
    const float* vcBase = v + (size_t)chBase * CPG3 +
                          ((size_t)qz * CPG + qy) * CPG;
    for (int i = tid; i < 4 * 16 * CPG; i += 256) {
        int ch = i / (16 * CPG);
        int rem = i - ch * (16 * CPG);
        int r = rem / CPG;
        int c = rem - r * CPG;
        s_cp[ch][r][c] = vcBase[(size_t)ch * CPG3 +
                                ((size_t)(r >> 2) * CPG + (r & 3)) * CPG + c];
    }
    __syncthreads();

    // ---- Phase B: fused z+y collapse, all 4 channels ----
    {
        const int brz = tid / CPG;          // 0..4 for active threads
        const int bcx = tid - brz * CPG;
        if (tid < 210) {
            float wz0 = s_W[brz][0], wz1 = s_W[brz][1];
            float wz2 = s_W[brz][2], wz3 = s_W[brz][3];
            #pragma unroll
            for (int ch = 0; ch < 4; ch++) {
                float tz[4];
                #pragma unroll
                for (int dy = 0; dy < 4; dy++) {
                    float acc =        wz0 * s_cp[ch][0 * 4 + dy][bcx];
                    acc = fmaf(wz1, s_cp[ch][1 * 4 + dy][bcx], acc);
                    acc = fmaf(wz2, s_cp[ch][2 * 4 + dy][bcx], acc);
                    acc = fmaf(wz3, s_cp[ch][3 * 4 + dy][bcx], acc);
                    tz[dy] = acc;
                }
                #pragma unroll
                for (int ry = 0; ry < 5; ry++) {
                    float acc =        s_W[ry][0] * tz[0];
                    acc = fmaf(s_W[ry][1], tz[1], acc);
                    acc = fmaf(s_W[ry][2], tz[2], acc);
                    acc = fmaf(s_W[ry][3], tz[3], acc);
                    s_row[ch][brz * 5 + ry][bcx] = acc;
                }
            }
        }
    }
    __syncthreads();

    // ---- Phase C: x expansion, 4 channels, no further barriers ----
    if (tid < 240) {
        const int x4 = tid % 48;
        const int rz = tid / 48;
        const int x0 = x4 * 4;
        const int q  = x0 / 5;              // q+4 <= 41
        const int cls = x4 % 5;
        const int z  = qz * 5 + rz;
        const int y0 = qy * 5;
        const bool zok = (z < IMG);
        const size_t zoff = (size_t)z * IMG2 + (size_t)y0 * IMG + (size_t)x0;

        float we[4][5];
        {
            const float* p = &s_we[cls * 20];
            #pragma unroll
            for (int j = 0; j < 4; j++)
                #pragma unroll
                for (int e = 0; e < 5; e++)
                    we[j][e] = p[j * 5 + e];
        }

        #pragma unroll
        for (int ch = 0; ch < 4; ch++) {
            float* op = out + (size_t)(chBase + ch) * IMG3 + zoff;
            const float* rbase = &s_row[ch][rz * 5][q];
            #pragma unroll
            for (int ry = 0; ry < 5; ry++) {
                const float* rp = rbase + ry * CPG;
                float r0 = rp[0], r1 = rp[1], r2 = rp[2], r3 = rp[3], r4 = rp[4];
                float4 o;
                o.x = fmaf(we[0][0], r0, fmaf(we[0][1], r1, fmaf(we[0][2], r2,
                      fmaf(we[0][3], r3, we[0][4] * r4))));
                o.y = fmaf(we[1][0], r0, fmaf(we[1][1], r1, fmaf(we[1][2], r2,
                      fmaf(we[1][3], r3, we[1][4] * r4))));
                o.z = fmaf(we[2][0], r0, fmaf(we[2][1], r1, fmaf(we[2][2], r2,
                      fmaf(we[2][3], r3, we[2][4] * r4))));
                o.w = fmaf(we[3][0], r0, fmaf(we[3][1], r1, fmaf(we[3][2], r2,
                      fmaf(we[3][3], r3, we[3][4] * r4))));
                if (zok && (y0 + ry < IMG))
                    __stcs(reinterpret_cast<float4*>(op + (size_t)ry * IMG), o);
            }
        }
    }
}

extern "C" void kernel_launch(void* const* d_in, const int* in_sizes, int n_in,
                              void* d_out, int out_size) {
    const float* v = (const float*)d_in[0];
    float* out = (float*)d_out;
    dim3 grid(39, 39, 3);   // (qy, qz, channel-group of 4)
    ffd_kernel<<<grid, 256>>>(v, out);
}

// round 5
// speedup vs baseline: 2.2584x; 1.0731x over previous
#include <cuda_runtime.h>

#define CPG 42
#define IMG 192
#define CPG3 (CPG * CPG * CPG)
#define IMG2 ((size_t)IMG * IMG)
#define IMG3 (IMG2 * IMG)

__global__ __launch_bounds__(256) void ffd_kernel(const float* __restrict__ v,
                                                  float* __restrict__ out) {
    const int qy = blockIdx.x;          // 0..38
    const int qz = blockIdx.y;          // 0..38
    const int chBase = blockIdx.z * 4;  // 0,4,8

    __shared__ float s_W[5][4];          // B-spline weights per residue
    __shared__ float s_we[100];          // phase-C class table [5 cls][4 j][5 e]
    __shared__ float s_cp[4][16][CPG];   // control points [ch][(dz*4+dy)][cx]
    __shared__ float s_row[4][25][CPG];  // zy-collapsed   [ch][rz*5+ry][cx]

    const int tid = threadIdx.x;

    // ---- one-time weight tables ----
    if (tid < 20) {
        int r = tid >> 2, d = tid & 3;
        float u = (float)r * 0.2f;
        float w;
        if (d == 0)      { float a = 1.0f - u; w = a * a * a * (1.0f / 6.0f); }
        else if (d == 1) { w = (3.0f * u * u * u - 6.0f * u * u + 4.0f) * (1.0f / 6.0f); }
        else if (d == 2) { w = (((-3.0f * u + 3.0f) * u + 3.0f) * u + 1.0f) * (1.0f / 6.0f); }
        else             { w = u * u * u * (1.0f / 6.0f); }
        s_W[r][d] = w;
    } else if (tid < 40) {
        int tt = tid - 20;
        int c = tt >> 2, j = tt & 3;
        int xx = 4 * c + j;
        int qq = xx / 5;
        int rx = xx - qq * 5;
        int s = qq - ((4 * c) / 5);     // 0 or 1
        float u = (float)rx * 0.2f;
        float a = 1.0f - u;
        float w0 = a * a * a * (1.0f / 6.0f);
        float w1 = (3.0f * u * u * u - 6.0f * u * u + 4.0f) * (1.0f / 6.0f);
        float w2 = (((-3.0f * u + 3.0f) * u + 3.0f) * u + 1.0f) * (1.0f / 6.0f);
        float w3 = u * u * u * (1.0f / 6.0f);
        float* p = &s_we[(c * 4 + j) * 5];
        p[0] = s ? 0.0f : w0;
        p[1] = s ? w0 : w1;
        p[2] = s ? w1 : w2;
        p[3] = s ? w2 : w3;
        p[4] = s ? w3 : 0.0f;
    }

    // ---- Phase A: load 4 channel slabs as float2 (4*16*21 = 1344 pairs) ----
    const float* vcBase = v + (size_t)chBase * CPG3 +
                          ((size_t)qz * CPG + qy) * CPG;
    {
        // offsets: ch*CPG3 + ((r>>2)*CPG + (r&3))*CPG + 2*c2 ; all even-aligned
        #pragma unroll
        for (int k = 0; k < 6; k++) {           // 6*256 = 1536 >= 1344
            int i = tid + k * 256;
            if (i < 4 * 16 * 21) {
                int ch = i / (16 * 21);
                int rem = i - ch * (16 * 21);
                int r = rem / 21;
                int c2 = rem - r * 21;
                const float2 val = *reinterpret_cast<const float2*>(
                    vcBase + (size_t)ch * CPG3 +
                    ((size_t)(r >> 2) * CPG + (r & 3)) * CPG + 2 * c2);
                *reinterpret_cast<float2*>(&s_cp[ch][r][2 * c2]) = val;
            }
        }
    }
    __syncthreads();

    // ---- Phase B: fused z+y collapse, float2 pairs, 420 tasks / 256 threads ----
    {
        #pragma unroll
        for (int k = 0; k < 2; k++) {
            int task = tid + k * 256;
            if (task < 420) {
                int rz  = task / 84;
                int rem = task - rz * 84;
                int ch  = rem / 21;
                int cxp = rem - ch * 21;
                const int cx = 2 * cxp;

                const float wz0 = s_W[rz][0], wz1 = s_W[rz][1];
                const float wz2 = s_W[rz][2], wz3 = s_W[rz][3];

                float2 tz[4];
                #pragma unroll
                for (int dy = 0; dy < 4; dy++) {
                    float2 c0 = *reinterpret_cast<const float2*>(&s_cp[ch][0 * 4 + dy][cx]);
                    float2 c1 = *reinterpret_cast<const float2*>(&s_cp[ch][1 * 4 + dy][cx]);
                    float2 c2 = *reinterpret_cast<const float2*>(&s_cp[ch][2 * 4 + dy][cx]);
                    float2 c3 = *reinterpret_cast<const float2*>(&s_cp[ch][3 * 4 + dy][cx]);
                    tz[dy].x = fmaf(wz3, c3.x, fmaf(wz2, c2.x, fmaf(wz1, c1.x, wz0 * c0.x)));
                    tz[dy].y = fmaf(wz3, c3.y, fmaf(wz2, c2.y, fmaf(wz1, c1.y, wz0 * c0.y)));
                }
                #pragma unroll
                for (int ry = 0; ry < 5; ry++) {
                    const float a0 = s_W[ry][0], a1 = s_W[ry][1];
                    const float a2 = s_W[ry][2], a3 = s_W[ry][3];
                    float2 o;
                    o.x = fmaf(a3, tz[3].x, fmaf(a2, tz[2].x, fmaf(a1, tz[1].x, a0 * tz[0].x)));
                    o.y = fmaf(a3, tz[3].y, fmaf(a2, tz[2].y, fmaf(a1, tz[1].y, a0 * tz[0].y)));
                    *reinterpret_cast<float2*>(&s_row[ch][rz * 5 + ry][cx]) = o;
                }
            }
        }
    }
    __syncthreads();

    // ---- Phase C: x expansion ----
    if (tid < 240) {
        const int x4 = tid % 48;
        const int rz = tid / 48;
        const int x0 = x4 * 4;
        const int q  = x0 / 5;              // q+4 <= 41
        const int cls = x4 % 5;
        const int z  = qz * 5 + rz;
        const int y0 = qy * 5;
        const size_t zoff = (size_t)z * IMG2 + (size_t)y0 * IMG + (size_t)x0;

        float we[4][5];
        {
            const float* p = &s_we[cls * 20];
            #pragma unroll
            for (int j = 0; j < 4; j++)
                #pragma unroll
                for (int e = 0; e < 5; e++)
                    we[j][e] = p[j * 5 + e];
        }

        if (qy < 38 && qz < 38) {
            // ---- interior: no guards ----
            #pragma unroll
            for (int ch = 0; ch < 4; ch++) {
                float* op = out + (size_t)(chBase + ch) * IMG3 + zoff;
                const float* rbase = &s_row[ch][rz * 5][q];
                #pragma unroll
                for (int ry = 0; ry < 5; ry++) {
                    const float* rp = rbase + ry * CPG;
                    float r0 = rp[0], r1 = rp[1], r2 = rp[2], r3 = rp[3], r4 = rp[4];
                    float4 o;
                    o.x = fmaf(we[0][0], r0, fmaf(we[0][1], r1, fmaf(we[0][2], r2,
                          fmaf(we[0][3], r3, we[0][4] * r4))));
                    o.y = fmaf(we[1][0], r0, fmaf(we[1][1], r1, fmaf(we[1][2], r2,
                          fmaf(we[1][3], r3, we[1][4] * r4))));
                    o.z = fmaf(we[2][0], r0, fmaf(we[2][1], r1, fmaf(we[2][2], r2,
                          fmaf(we[2][3], r3, we[2][4] * r4))));
                    o.w = fmaf(we[3][0], r0, fmaf(we[3][1], r1, fmaf(we[3][2], r2,
                          fmaf(we[3][3], r3, we[3][4] * r4))));
                    __stcs(reinterpret_cast<float4*>(op), o);
                    op += IMG;
                }
            }
        } else {
            // ---- boundary: guarded ----
            const bool zok = (z < IMG);
            #pragma unroll
            for (int ch = 0; ch < 4; ch++) {
                float* op = out + (size_t)(chBase + ch) * IMG3 + zoff;
                const float* rbase = &s_row[ch][rz * 5][q];
                #pragma unroll
                for (int ry = 0; ry < 5; ry++) {
                    const float* rp = rbase + ry * CPG;
                    float r0 = rp[0], r1 = rp[1], r2 = rp[2], r3 = rp[3], r4 = rp[4];
                    float4 o;
                    o.x = fmaf(we[0][0], r0, fmaf(we[0][1], r1, fmaf(we[0][2], r2,
                          fmaf(we[0][3], r3, we[0][4] * r4))));
                    o.y = fmaf(we[1][0], r0, fmaf(we[1][1], r1, fmaf(we[1][2], r2,
                          fmaf(we[1][3], r3, we[1][4] * r4))));
                    o.z = fmaf(we[2][0], r0, fmaf(we[2][1], r1, fmaf(we[2][2], r2,
                          fmaf(we[2][3], r3, we[2][4] * r4))));
                    o.w = fmaf(we[3][0], r0, fmaf(we[3][1], r1, fmaf(we[3][2], r2,
                          fmaf(we[3][3], r3, we[3][4] * r4))));
                    if (zok && (y0 + ry < IMG))
                        __stcs(reinterpret_cast<float4*>(op), o);
                    op += IMG;
                }
            }
        }
    }
}

extern "C" void kernel_launch(void* const* d_in, const int* in_sizes, int n_in,
                              void* d_out, int out_size) {
    const float* v = (const float*)d_in[0];
    float* out = (float*)d_out;
    dim3 grid(39, 39, 3);   // (qy, qz, channel-group of 4)
    ffd_kernel<<<grid, 256>>>(v, out);
}

// round 6
// speedup vs baseline: 2.4587x; 1.0887x over previous
#include <cuda_runtime.h>

#define CPG 42
#define IMG 192
#define CPG3 (CPG * CPG * CPG)
#define IMG2 ((size_t)IMG * IMG)
#define IMG3 (IMG2 * IMG)

__global__ __launch_bounds__(256) void ffd_kernel(const float* __restrict__ v,
                                                  float* __restrict__ out) {
    const int qy = blockIdx.x;          // 0..38
    const int qz = blockIdx.y;          // 0..38
    const int chBase = blockIdx.z * 4;  // 0,4,8

    __shared__ float s_W[5][4];          // B-spline weights per residue
    __shared__ float s_we[100];          // phase-C class table [5 cls][4 j][5 e]
    __shared__ float s_cp[4][16][CPG];   // control points [ch][(dz*4+dy)][cx]
    __shared__ float s_row[4][25][CPG];  // zy-collapsed   [ch][rz*5+ry][cx]

    const int tid = threadIdx.x;

    // ---- one-time weight tables ----
    if (tid < 20) {
        int r = tid >> 2, d = tid & 3;
        float u = (float)r * 0.2f;
        float w;
        if (d == 0)      { float a = 1.0f - u; w = a * a * a * (1.0f / 6.0f); }
        else if (d == 1) { w = (3.0f * u * u * u - 6.0f * u * u + 4.0f) * (1.0f / 6.0f); }
        else if (d == 2) { w = (((-3.0f * u + 3.0f) * u + 3.0f) * u + 1.0f) * (1.0f / 6.0f); }
        else             { w = u * u * u * (1.0f / 6.0f); }
        s_W[r][d] = w;
    } else if (tid < 40) {
        int tt = tid - 20;
        int c = tt >> 2, j = tt & 3;
        int xx = 4 * c + j;
        int qq = xx / 5;
        int rx = xx - qq * 5;
        int s = qq - ((4 * c) / 5);     // 0 or 1
        float u = (float)rx * 0.2f;
        float a = 1.0f - u;
        float w0 = a * a * a * (1.0f / 6.0f);
        float w1 = (3.0f * u * u * u - 6.0f * u * u + 4.0f) * (1.0f / 6.0f);
        float w2 = (((-3.0f * u + 3.0f) * u + 3.0f) * u + 1.0f) * (1.0f / 6.0f);
        float w3 = u * u * u * (1.0f / 6.0f);
        float* p = &s_we[(c * 4 + j) * 5];
        p[0] = s ? 0.0f : w0;
        p[1] = s ? w0 : w1;
        p[2] = s ? w1 : w2;
        p[3] = s ? w2 : w3;
        p[4] = s ? w3 : 0.0f;
    }

    // ---- Phase A: load 4 channel slabs as float2 (4*16*21 = 1344 pairs) ----
    const float* vcBase = v + (size_t)chBase * CPG3 +
                          ((size_t)qz * CPG + qy) * CPG;
    {
        #pragma unroll
        for (int k = 0; k < 6; k++) {           // 6*256 = 1536 >= 1344
            int i = tid + k * 256;
            if (i < 4 * 16 * 21) {
                int ch = i / (16 * 21);
                int rem = i - ch * (16 * 21);
                int r = rem / 21;
                int c2 = rem - r * 21;
                const float2 val = *reinterpret_cast<const float2*>(
                    vcBase + (size_t)ch * CPG3 +
                    ((size_t)(r >> 2) * CPG + (r & 3)) * CPG + 2 * c2);
                *reinterpret_cast<float2*>(&s_cp[ch][r][2 * c2]) = val;
            }
        }
    }
    __syncthreads();

    // ---- Phase B: fused z+y collapse. Task = (ch, cx): 168 scalar tasks.
    //      Each task reads its 16 control points ONCE, computes all 25 rows.
    if (tid < 168) {
        const int ch = tid / CPG;
        const int cx = tid - ch * CPG;

        // stream dz-slabs into tzdy[rz][dy] accumulators
        float tzdy[5][4];
        {
            float c0 = s_cp[ch][0][cx], c1 = s_cp[ch][1][cx];
            float c2 = s_cp[ch][2][cx], c3 = s_cp[ch][3][cx];
            #pragma unroll
            for (int rz = 0; rz < 5; rz++) {
                float w = s_W[rz][0];
                tzdy[rz][0] = w * c0; tzdy[rz][1] = w * c1;
                tzdy[rz][2] = w * c2; tzdy[rz][3] = w * c3;
            }
        }
        #pragma unroll
        for (int dz = 1; dz < 4; dz++) {
            float c0 = s_cp[ch][dz * 4 + 0][cx], c1 = s_cp[ch][dz * 4 + 1][cx];
            float c2 = s_cp[ch][dz * 4 + 2][cx], c3 = s_cp[ch][dz * 4 + 3][cx];
            #pragma unroll
            for (int rz = 0; rz < 5; rz++) {
                float w = s_W[rz][dz];
                tzdy[rz][0] = fmaf(w, c0, tzdy[rz][0]);
                tzdy[rz][1] = fmaf(w, c1, tzdy[rz][1]);
                tzdy[rz][2] = fmaf(w, c2, tzdy[rz][2]);
                tzdy[rz][3] = fmaf(w, c3, tzdy[rz][3]);
            }
        }
        // y-collapse -> 25 rows
        #pragma unroll
        for (int rz = 0; rz < 5; rz++) {
            #pragma unroll
            for (int ry = 0; ry < 5; ry++) {
                float acc =        s_W[ry][0] * tzdy[rz][0];
                acc = fmaf(s_W[ry][1], tzdy[rz][1], acc);
                acc = fmaf(s_W[ry][2], tzdy[rz][2], acc);
                acc = fmaf(s_W[ry][3], tzdy[rz][3], acc);
                s_row[ch][rz * 5 + ry][cx] = acc;
            }
        }
    }
    __syncthreads();

    // ---- Phase C: x expansion ----
    if (tid < 240) {
        const int x4 = tid % 48;
        const int rz = tid / 48;
        const int x0 = x4 * 4;
        const int q  = x0 / 5;              // q+4 <= 41
        const int cls = x4 % 5;
        const int z  = qz * 5 + rz;
        const int y0 = qy * 5;
        const size_t zoff = (size_t)z * IMG2 + (size_t)y0 * IMG + (size_t)x0;

        float we[4][5];
        {
            const float* p = &s_we[cls * 20];
            #pragma unroll
            for (int j = 0; j < 4; j++)
                #pragma unroll
                for (int e = 0; e < 5; e++)
                    we[j][e] = p[j * 5 + e];
        }

        if (qy < 38 && qz < 38) {
            // ---- interior: no guards ----
            #pragma unroll
            for (int ch = 0; ch < 4; ch++) {
                float* op = out + (size_t)(chBase + ch) * IMG3 + zoff;
                const float* rbase = &s_row[ch][rz * 5][q];
                #pragma unroll
                for (int ry = 0; ry < 5; ry++) {
                    const float* rp = rbase + ry * CPG;
                    float r0 = rp[0], r1 = rp[1], r2 = rp[2], r3 = rp[3], r4 = rp[4];
                    float4 o;
                    o.x = fmaf(we[0][0], r0, fmaf(we[0][1], r1, fmaf(we[0][2], r2,
                          fmaf(we[0][3], r3, we[0][4] * r4))));
                    o.y = fmaf(we[1][0], r0, fmaf(we[1][1], r1, fmaf(we[1][2], r2,
                          fmaf(we[1][3], r3, we[1][4] * r4))));
                    o.z = fmaf(we[2][0], r0, fmaf(we[2][1], r1, fmaf(we[2][2], r2,
                          fmaf(we[2][3], r3, we[2][4] * r4))));
                    o.w = fmaf(we[3][0], r0, fmaf(we[3][1], r1, fmaf(we[3][2], r2,
                          fmaf(we[3][3], r3, we[3][4] * r4))));
                    __stcs(reinterpret_cast<float4*>(op), o);
                    op += IMG;
                }
            }
        } else {
            // ---- boundary: guarded ----
            const bool zok = (z < IMG);
            #pragma unroll
            for (int ch = 0; ch < 4; ch++) {
                float* op = out + (size_t)(chBase + ch) * IMG3 + zoff;
                const float* rbase = &s_row[ch][rz * 5][q];
                #pragma unroll
                for (int ry = 0; ry < 5; ry++) {
                    const float* rp = rbase + ry * CPG;
                    float r0 = rp[0], r1 = rp[1], r2 = rp[2], r3 = rp[3], r4 = rp[4];
                    float4 o;
                    o.x = fmaf(we[0][0], r0, fmaf(we[0][1], r1, fmaf(we[0][2], r2,
                          fmaf(we[0][3], r3, we[0][4] * r4))));
                    o.y = fmaf(we[1][0], r0, fmaf(we[1][1], r1, fmaf(we[1][2], r2,
                          fmaf(we[1][3], r3, we[1][4] * r4))));
                    o.z = fmaf(we[2][0], r0, fmaf(we[2][1], r1, fmaf(we[2][2], r2,
                          fmaf(we[2][3], r3, we[2][4] * r4))));
                    o.w = fmaf(we[3][0], r0, fmaf(we[3][1], r1, fmaf(we[3][2], r2,
                          fmaf(we[3][3], r3, we[3][4] * r4))));
                    if (zok && (y0 + ry < IMG))
                        __stcs(reinterpret_cast<float4*>(op), o);
                    op += IMG;
                }
            }
        }
    }
}

extern "C" void kernel_launch(void* const* d_in, const int* in_sizes, int n_in,
                              void* d_out, int out_size) {
    const float* v = (const float*)d_in[0];
    float* out = (float*)d_out;
    dim3 grid(39, 39, 3);   // (qy, qz, channel-group of 4)
    ffd_kernel<<<grid, 256>>>(v, out);
}